// round 8
// baseline (speedup 1.0000x reference)
#include <cuda_runtime.h>
#include <math.h>

// ---------------------------------------------------------------------------
// EnhancedSNNCifar: T=8 SNN forward, fp32 throughout.
// R5: conv inner loop rewritten with packed fp32x2 FMAs (fma.rn.f32x2,
//     Blackwell FFMA2 path) — pairs of output channels per instruction.
//     Bit-identical accumulation order vs scalar version.
// ---------------------------------------------------------------------------

#define TSTEPS 8

typedef unsigned long long ull;

__device__ float  g_y [33554432];
__device__ float  g_s [33554432];
__device__ float  g_sp[ 8388608];
__device__ float  g_fc1 [131072];
__device__ float  g_fc1s[131072];
__device__ float  g_fc2 [ 10240];
__device__ double g_ps [128 * 64];
__device__ double g_ps2[128 * 64];
__device__ float  g_inv  [128];
__device__ float  g_shift[128];

__device__ __forceinline__ ull ffma2(ull a, ull b, ull c) {
    ull d;
    asm("fma.rn.f32x2 %0, %1, %2, %3;" : "=l"(d) : "l"(a), "l"(b), "l"(c));
    return d;
}
__device__ __forceinline__ ull pack2(float x) {
    ull d;
    asm("mov.b64 %0, {%1, %1};" : "=l"(d) : "f"(x));
    return d;
}
__device__ __forceinline__ void unpack2(ull v, float& lo, float& hi) {
    asm("mov.b64 {%0, %1}, %2;" : "=f"(lo), "=f"(hi) : "l"(v));
}

// ---------------------------------------------------------------------------
// Direct 3x3 conv, pad=1, stride=1.  Thread: 2x2 pixels x 8 couts (4 f32x2
// accumulator pairs).  Block = 256 threads = IMGS images * QPI quads.
// CH input channels staged per sync round; staging index math precomputed.
// ---------------------------------------------------------------------------
template<int CIN, int COUT, int H, int W, int IMGS, int CH>
__global__ __launch_bounds__(256)
void conv3x3_kernel(const float* __restrict__ in, const float* __restrict__ wt,
                    const float* __restrict__ bias, float* __restrict__ out)
{
    constexpr int QPI = (H / 2) * (W / 2);
    static_assert(IMGS * QPI == 256, "block mapping");
    constexpr int PW = W + 2, PH = H + 2;
    constexpr int IN_TILE = PH * PW;
    constexpr int HW = H * W;
    constexpr int TOT = IMGS * IN_TILE;
    constexpr int NPOS = (TOT + 255) / 256;

    __shared__ float s_in[CH][TOT];
    __shared__ __align__(16) float s_w[CH][9][8];

    const int tid = threadIdx.x;
    const int cog = blockIdx.y;
    const int m0  = blockIdx.x * IMGS;

    // ---- precompute staging tables (once) ----
    int  gpix[NPOS];
    bool pval[NPOS];
#pragma unroll
    for (int k = 0; k < NPOS; k++) {
        const int i = tid + k * 256;
        const int il = i / IN_TILE, r = i % IN_TILE;
        const int py = r / PW, px = r % PW;
        const int iy = py - 1, ix = px - 1;
        pval[k] = (i < TOT) && (iy >= 0) && (iy < H) && (ix >= 0) && (ix < W);
        gpix[k] = il * (CIN * HW) + iy * W + ix;
    }
    const int wj = tid / 9, wk = tid % 9;
    const int wbase = ((cog * 8 + wj) * CIN) * 9 + wk;

    const int img_l = tid / QPI;
    const int q     = tid % QPI;
    const int qy = q / (W / 2), qx = q % (W / 2);
    const int oy = qy * 2, ox = qx * 2;
    const float* inb = in + (size_t)m0 * CIN * HW;

    // acc2[pos][p] : pos = 2x2 pixel, p = cout pair (couts 2p, 2p+1)
    ull acc2[4][4];
#pragma unroll
    for (int p = 0; p < 4; p++)
#pragma unroll
        for (int j = 0; j < 4; j++) acc2[p][j] = 0ULL;

#pragma unroll 1
    for (int c0 = 0; c0 < CIN; c0 += CH) {
        __syncthreads();
        if (tid < 72) {
#pragma unroll
            for (int c = 0; c < CH; c++)
                s_w[c][wk][wj] = wt[wbase + (c0 + c) * 9];
        }
#pragma unroll
        for (int c = 0; c < CH; c++) {
            const float* inc = inb + (size_t)(c0 + c) * HW;
#pragma unroll
            for (int k = 0; k < NPOS; k++) {
                const int i = tid + k * 256;
                if (i < TOT)
                    s_in[c][i] = pval[k] ? __ldg(inc + gpix[k]) : 0.f;
            }
        }
        __syncthreads();

#pragma unroll 1
        for (int c = 0; c < CH; ++c) {
            // 4x4 input window, broadcast-packed into f32x2
            ull xp[4][4];
            const float* sb = &s_in[c][img_l * IN_TILE + oy * PW + ox];
#pragma unroll
            for (int dy = 0; dy < 4; dy++) {
                float2 a = *(const float2*)(sb + dy * PW);
                float2 b = *(const float2*)(sb + dy * PW + 2);
                xp[dy][0] = pack2(a.x); xp[dy][1] = pack2(a.y);
                xp[dy][2] = pack2(b.x); xp[dy][3] = pack2(b.y);
            }
#pragma unroll
            for (int k = 0; k < 9; k++) {
                const int ky = k / 3, kx = k % 3;
                const ull* wp = (const ull*)&s_w[c][k][0];
                const ull w0 = wp[0], w1 = wp[1], w2 = wp[2], w3 = wp[3];
#pragma unroll
                for (int py = 0; py < 2; py++)
#pragma unroll
                    for (int px = 0; px < 2; px++) {
                        const ull xb = xp[py + ky][px + kx];
                        const int pos = py * 2 + px;
                        acc2[pos][0] = ffma2(xb, w0, acc2[pos][0]);
                        acc2[pos][1] = ffma2(xb, w1, acc2[pos][1]);
                        acc2[pos][2] = ffma2(xb, w2, acc2[pos][2]);
                        acc2[pos][3] = ffma2(xb, w3, acc2[pos][3]);
                    }
            }
        }
    }

    // unpack accumulators -> acc[pos][cout]
    float acc[4][8];
#pragma unroll
    for (int pos = 0; pos < 4; pos++)
#pragma unroll
        for (int p = 0; p < 4; p++)
            unpack2(acc2[pos][p], acc[pos][2 * p], acc[pos][2 * p + 1]);

    float bj[8];
#pragma unroll
    for (int j = 0; j < 8; j++) bj[j] = bias[cog * 8 + j];

#pragma unroll
    for (int j = 0; j < 8; j++) {
        const int co = cog * 8 + j;
        const size_t base = ((size_t)(m0 + img_l) * COUT + co) * HW;
#pragma unroll
        for (int py = 0; py < 2; py++) {
            float2 v2 = make_float2(acc[py * 2 + 0][j] + bj[j], acc[py * 2 + 1][j] + bj[j]);
            *(float2*)&out[base + (oy + py) * W + ox] = v2;
        }
    }
}

// ---------------------------------------------------------------------------
__global__ void bn_stats_kernel(const float* __restrict__ y, int C, int HW4, int M)
{
    const int c = blockIdx.x, b = blockIdx.y;
    const long total4 = (long)M * HW4;
    const long chunk = (total4 + 63) / 64;
    long beg = (long)b * chunk;
    long end = beg + chunk; if (end > total4) end = total4;

    const float4* y4 = (const float4*)y;
    double s = 0.0, s2 = 0.0;
    for (long e = beg + threadIdx.x; e < end; e += 256) {
        long m = e / HW4; int off = (int)(e % HW4);
        float4 v = y4[((size_t)m * C + c) * HW4 + off];
        double a = v.x, bb = v.y, cc = v.z, dd = v.w;
        s += (a + bb) + (cc + dd);
        s2 += (a * a + bb * bb) + (cc * cc + dd * dd);
    }
    __shared__ double ss[256], ss2[256];
    ss[threadIdx.x] = s; ss2[threadIdx.x] = s2;
    __syncthreads();
    for (int st = 128; st > 0; st >>= 1) {
        if (threadIdx.x < st) {
            ss[threadIdx.x]  += ss[threadIdx.x + st];
            ss2[threadIdx.x] += ss2[threadIdx.x + st];
        }
        __syncthreads();
    }
    if (threadIdx.x == 0) {
        g_ps [c * 64 + b] = ss[0];
        g_ps2[c * 64 + b] = ss2[0];
    }
}

__global__ void bn_finalize_kernel(const float* __restrict__ g,
                                   const float* __restrict__ be, int C, double n)
{
    int c = threadIdx.x;
    if (c >= C) return;
    double s = 0.0, s2 = 0.0;
    for (int b = 0; b < 64; b++) { s += g_ps[c * 64 + b]; s2 += g_ps2[c * 64 + b]; }
    double mean = s / n;
    double var  = s2 / n - mean * mean;
    float invf = g[c] / sqrtf((float)var + 1e-5f);
    g_inv[c]   = invf;
    g_shift[c] = be[c] - (float)mean * invf;
}

__global__ void bn_lif_kernel(const float* __restrict__ y, float* __restrict__ s,
                              int C, int HW, long tstride)
{
    const int sites = 128 * C * HW;
    const int idx = blockIdx.x * 256 + threadIdx.x;
    if (idx >= sites) return;
    const int c = (idx / HW) % C;
    const float vi = g_inv[c], sh = g_shift[c];
    float v = 0.f;
#pragma unroll
    for (int t = 0; t < TSTEPS; t++) {
        float x = fmaf(y[(size_t)t * tstride + idx], vi, sh);
        v = v + (x - v) * 0.5f;
        float spike = (v >= 1.0f) ? 1.0f : 0.0f;
        s[(size_t)sites * t + idx] = spike;
        if (v >= 1.0f) v = 0.0f;
    }
}

__global__ void bn_lif_pool_kernel(const float* __restrict__ y, float* __restrict__ out,
                                   int C, int H, int W)
{
    const int OH = H / 2, OW = W / 2;
    const int ohw = OH * OW;
    const int sites = 128 * C * ohw;
    const int idx = blockIdx.x * 256 + threadIdx.x;
    if (idx >= sites) return;
    const int c = (idx / ohw) % C;
    const int n = idx / (C * ohw);
    const int r = idx % ohw;
    const int oy = r / OW, ox = r % OW;
    const size_t base = ((size_t)(n * C + c) * H + 2 * oy) * W + 2 * ox;
    const long tstr = (long)128 * C * H * W;
    const float vi = g_inv[c], sh = g_shift[c];
    float v0 = 0.f, v1 = 0.f, v2 = 0.f, v3 = 0.f;
#pragma unroll
    for (int t = 0; t < TSTEPS; t++) {
        const float* p = y + (size_t)t * tstr + base;
        float x0 = fmaf(p[0],     vi, sh);
        float x1 = fmaf(p[1],     vi, sh);
        float x2 = fmaf(p[W],     vi, sh);
        float x3 = fmaf(p[W + 1], vi, sh);
        v0 = v0 + (x0 - v0) * 0.5f;
        v1 = v1 + (x1 - v1) * 0.5f;
        v2 = v2 + (x2 - v2) * 0.5f;
        v3 = v3 + (x3 - v3) * 0.5f;
        float sp = ((v0 >= 1.0f) || (v1 >= 1.0f) || (v2 >= 1.0f) || (v3 >= 1.0f)) ? 1.0f : 0.0f;
        out[(size_t)t * sites + idx] = sp;
        if (v0 >= 1.0f) v0 = 0.0f;
        if (v1 >= 1.0f) v1 = 0.0f;
        if (v2 >= 1.0f) v2 = 0.0f;
        if (v3 >= 1.0f) v3 = 0.0f;
    }
}

__global__ __launch_bounds__(128)
void fc1_kernel(const float* __restrict__ in, const float* __restrict__ w,
                const float* __restrict__ b, float* __restrict__ out)
{
    __shared__ float4 s_in[4][512];
    const int r0 = blockIdx.x * 4;
    for (int i = threadIdx.x; i < 4 * 512; i += 128) {
        int rr = i / 512, ff = i % 512;
        s_in[rr][ff] = ((const float4*)in)[(size_t)(r0 + rr) * 512 + ff];
    }
    __syncthreads();
    const int o = threadIdx.x;
    const float4* wr = (const float4*)(w + (size_t)o * 2048);
    float a0 = 0.f, a1 = 0.f, a2 = 0.f, a3 = 0.f;
#pragma unroll 4
    for (int f = 0; f < 512; f++) {
        float4 wv = wr[f];
        float4 x0 = s_in[0][f], x1 = s_in[1][f], x2 = s_in[2][f], x3 = s_in[3][f];
        a0 = fmaf(x0.x, wv.x, fmaf(x0.y, wv.y, fmaf(x0.z, wv.z, fmaf(x0.w, wv.w, a0))));
        a1 = fmaf(x1.x, wv.x, fmaf(x1.y, wv.y, fmaf(x1.z, wv.z, fmaf(x1.w, wv.w, a1))));
        a2 = fmaf(x2.x, wv.x, fmaf(x2.y, wv.y, fmaf(x2.z, wv.z, fmaf(x2.w, wv.w, a2))));
        a3 = fmaf(x3.x, wv.x, fmaf(x3.y, wv.y, fmaf(x3.z, wv.z, fmaf(x3.w, wv.w, a3))));
    }
    const float bo = b[o];
    out[(size_t)(r0 + 0) * 128 + o] = a0 + bo;
    out[(size_t)(r0 + 1) * 128 + o] = a1 + bo;
    out[(size_t)(r0 + 2) * 128 + o] = a2 + bo;
    out[(size_t)(r0 + 3) * 128 + o] = a3 + bo;
}

__global__ void fc2_kernel(const float* __restrict__ in, const float* __restrict__ w,
                           const float* __restrict__ b, float* __restrict__ out)
{
    const int idx = blockIdx.x * 256 + threadIdx.x;
    if (idx >= 10240) return;
    const int r = idx / 10, o = idx % 10;
    const float4* ir = (const float4*)(in + (size_t)r * 128);
    const float4* wr = (const float4*)(w + (size_t)o * 128);
    float a = 0.f;
#pragma unroll
    for (int f = 0; f < 32; f++) {
        float4 x = ir[f], wv = wr[f];
        a = fmaf(x.x, wv.x, fmaf(x.y, wv.y, fmaf(x.z, wv.z, fmaf(x.w, wv.w, a))));
    }
    out[idx] = a + b[o];
}

__global__ void lif_kernel(const float* __restrict__ y, float* __restrict__ s, int sites)
{
    const int idx = blockIdx.x * 256 + threadIdx.x;
    if (idx >= sites) return;
    float v = 0.f;
#pragma unroll
    for (int t = 0; t < TSTEPS; t++) {
        float x = y[(size_t)t * sites + idx];
        v = v + (x - v) * 0.5f;
        float spike = (v >= 1.0f) ? 1.0f : 0.0f;
        s[(size_t)t * sites + idx] = spike;
        if (v >= 1.0f) v = 0.0f;
    }
}

__global__ void lif_mean_kernel(const float* __restrict__ y, float* __restrict__ out,
                                int sites)
{
    const int idx = blockIdx.x * 256 + threadIdx.x;
    if (idx >= sites) return;
    float v = 0.f, cnt = 0.f;
#pragma unroll
    for (int t = 0; t < TSTEPS; t++) {
        float x = y[(size_t)t * sites + idx];
        v = v + (x - v) * 0.5f;
        if (v >= 1.0f) { cnt += 1.0f; v = 0.0f; }
    }
    out[idx] = cnt * 0.125f;
}

// ---------------------------------------------------------------------------
extern "C" void kernel_launch(void* const* d_in, const int* in_sizes, int n_in,
                              void* d_out, int out_size)
{
    const float* x = (const float*)d_in[0];
    const float* w[7];  const float* bb[7];  const float* gg[7];  const float* be[7];
    for (int L = 1; L <= 6; L++) {
        w [L] = (const float*)d_in[1 + 4 * (L - 1) + 0];
        bb[L] = (const float*)d_in[1 + 4 * (L - 1) + 1];
        gg[L] = (const float*)d_in[1 + 4 * (L - 1) + 2];
        be[L] = (const float*)d_in[1 + 4 * (L - 1) + 3];
    }
    const float* fc1_w = (const float*)d_in[25];
    const float* fc1_b = (const float*)d_in[26];
    const float* fc2_w = (const float*)d_in[27];
    const float* fc2_b = (const float*)d_in[28];
    float* out = (float*)d_out;

    float *y, *s, *sp, *f1, *f1s, *f2;
    cudaGetSymbolAddress((void**)&y,   g_y);
    cudaGetSymbolAddress((void**)&s,   g_s);
    cudaGetSymbolAddress((void**)&sp,  g_sp);
    cudaGetSymbolAddress((void**)&f1,  g_fc1);
    cudaGetSymbolAddress((void**)&f1s, g_fc1s);
    cudaGetSymbolAddress((void**)&f2,  g_fc2);

    // ---- Layer 1 ----
    conv3x3_kernel<3, 32, 32, 32, 1, 3><<<dim3(128, 4), 256>>>(x, w[1], bb[1], y);
    bn_stats_kernel<<<dim3(32, 64), 256>>>(y, 32, 256, 128);
    bn_finalize_kernel<<<1, 128>>>(gg[1], be[1], 32, 128.0 * 1024.0);
    bn_lif_kernel<<<16384, 256>>>(y, s, 32, 1024, 0);

    // ---- Layer 2 (+pool) ----
    conv3x3_kernel<32, 32, 32, 32, 1, 8><<<dim3(1024, 4), 256>>>(s, w[2], bb[2], y);
    bn_stats_kernel<<<dim3(32, 64), 256>>>(y, 32, 256, 1024);
    bn_finalize_kernel<<<1, 128>>>(gg[2], be[2], 32, 1024.0 * 1024.0);
    bn_lif_pool_kernel<<<4096, 256>>>(y, sp, 32, 32, 32);

    // ---- Layer 3 ----
    conv3x3_kernel<32, 64, 16, 16, 4, 8><<<dim3(256, 8), 256>>>(sp, w[3], bb[3], y);
    bn_stats_kernel<<<dim3(64, 64), 256>>>(y, 64, 64, 1024);
    bn_finalize_kernel<<<1, 128>>>(gg[3], be[3], 64, 1024.0 * 256.0);
    bn_lif_kernel<<<8192, 256>>>(y, s, 64, 256, (long)128 * 64 * 256);

    // ---- Layer 4 (+pool) ----
    conv3x3_kernel<64, 64, 16, 16, 4, 8><<<dim3(256, 8), 256>>>(s, w[4], bb[4], y);
    bn_stats_kernel<<<dim3(64, 64), 256>>>(y, 64, 64, 1024);
    bn_finalize_kernel<<<1, 128>>>(gg[4], be[4], 64, 1024.0 * 256.0);
    bn_lif_pool_kernel<<<2048, 256>>>(y, sp, 64, 16, 16);

    // ---- Layer 5 ----
    conv3x3_kernel<64, 128, 8, 8, 16, 4><<<dim3(64, 16), 256>>>(sp, w[5], bb[5], y);
    bn_stats_kernel<<<dim3(128, 64), 256>>>(y, 128, 16, 1024);
    bn_finalize_kernel<<<1, 128>>>(gg[5], be[5], 128, 1024.0 * 64.0);
    bn_lif_kernel<<<4096, 256>>>(y, s, 128, 64, (long)128 * 128 * 64);

    // ---- Layer 6 (+pool) ----
    conv3x3_kernel<128, 128, 8, 8, 16, 4><<<dim3(64, 16), 256>>>(s, w[6], bb[6], y);
    bn_stats_kernel<<<dim3(128, 64), 256>>>(y, 128, 16, 1024);
    bn_finalize_kernel<<<1, 128>>>(gg[6], be[6], 128, 1024.0 * 64.0);
    bn_lif_pool_kernel<<<1024, 256>>>(y, sp, 128, 8, 8);

    // ---- FC head ----
    fc1_kernel<<<256, 128>>>(sp, fc1_w, fc1_b, f1);
    lif_kernel<<<64, 256>>>(f1, f1s, 16384);
    fc2_kernel<<<40, 256>>>(f1s, fc2_w, fc2_b, f2);
    lif_mean_kernel<<<5, 256>>>(f2, out, 1280);
}

// round 15
// speedup vs baseline: 1.1520x; 1.1520x over previous
#include <cuda.h>
#include <cuda_runtime.h>
#include <cuda_bf16.h>
#include <math.h>
#include <cstdint>

#define TSTEPS 8
#define NB 256

// ---------------------------------------------------------------------------
// device scratch
// ---------------------------------------------------------------------------
__device__ float  g_y [33554432];      // conv pre-act, channel-last (128MB)
__device__ uint4  g_pA4[9500000];      // padded spike tensor A (152MB)
__device__ uint4  g_pB4[2700000];      // padded spike tensor B (43MB)
__device__ uint4  g_wsp4[125000];      // pre-split weights (2MB)
__device__ float  g_fc1[131072];
__device__ float  g_fc1s[131072];
__device__ float  g_fc2[10240];
__device__ double g_ps [128 * NB];
__device__ double g_ps2[128 * NB];
__device__ float  g_inv[128];
__device__ float  g_shift[128];

// ---------------------------------------------------------------------------
// weight prep: fp32 w[co][ci][3][3] -> images ordered (img = tap*KC+kc, split),
// each packed [COUT][64] bf16 row-major.  Exact 3-way split (w = b0+b1+b2).
// ---------------------------------------------------------------------------
__global__ void wprep_kernel(const float* __restrict__ w, __nv_bfloat16* __restrict__ dst,
                             int COUT, int CINR, int KC)
{
    const int per = COUT * 64;
    const int total = 9 * KC * per;
    for (int i = blockIdx.x * 256 + threadIdx.x; i < total; i += gridDim.x * 256) {
        const int img = i / per;
        const int rr = i % per;
        const int tap = img / KC;
        const int kc = img % KC;
        const int co = rr / 64;
        const int cil = rr % 64;
        const int ci = kc * 64 + cil;
        float wv = 0.f;
        if (ci < CINR) wv = w[((size_t)co * CINR + ci) * 9 + tap];
        __nv_bfloat16 b0 = __float2bfloat16(wv);
        float r1 = wv - __bfloat162float(b0);
        __nv_bfloat16 b1 = __float2bfloat16(r1);
        __nv_bfloat16 b2 = __float2bfloat16(r1 - __bfloat162float(b1));
        dst[(size_t)(img * 3 + 0) * per + co * 64 + cil] = b0;
        dst[(size_t)(img * 3 + 1) * per + co * 64 + cil] = b1;
        dst[(size_t)(img * 3 + 2) * per + co * 64 + cil] = b2;
    }
}

// ---------------------------------------------------------------------------
// conv via warp-level HMMA (mma.sync m16n8k16 bf16->f32, base-target legal).
// CTA = 1 output pixel x one 128-row tn tile; 8 warps x m16.
// Per (tap,kc): stage A [128x64] (stride-72 rows), per split stage B [COUTx64],
// 4 k16 steps x COUT/8 n-tiles of MMA.  Products exact (spikes in {0,1}).
// ---------------------------------------------------------------------------
#define CONV_HMMA_BODY(COUTC, KCC) \
{ \
    __shared__ __align__(16) __nv_bfloat16 sA[128 * 72]; \
    __shared__ __align__(16) __nv_bfloat16 sB[COUTC * 72]; \
    const int tid = threadIdx.x; \
    const int warp = tid >> 5; \
    const int lane = tid & 31; \
    const int gid = lane >> 2; \
    const int qid = lane & 3; \
    const int pix = blockIdx.x; \
    const int m0 = blockIdx.y * 128; \
    const int py = pix / W; \
    const int px = pix % W; \
    const int Wp = W + 2; \
    const int CINP = KCC * 64; \
    float dacc[COUTC / 8][4]; \
    _Pragma("unroll") \
    for (int nt = 0; nt < COUTC / 8; nt++) { \
        dacc[nt][0] = 0.f; dacc[nt][1] = 0.f; dacc[nt][2] = 0.f; dacc[nt][3] = 0.f; \
    } \
    for (int img = 0; img < 9 * KCC; img++) { \
        const int tap = img / KCC; \
        const int kc = img % KCC; \
        const int ky = tap / 3; \
        const int kx = tap % 3; \
        const __nv_bfloat16* srcA = inPad \
            + ((size_t)((py + ky) * Wp + (px + kx)) * 1024 + m0) * (size_t)CINP + kc * 64; \
        for (int split = 0; split < 3; split++) { \
            __syncthreads(); \
            if (split == 0) { \
                _Pragma("unroll") \
                for (int k = 0; k < 4; k++) { \
                    const int ch = tid + k * 256; \
                    const int row = ch >> 3; \
                    const int c8 = (ch & 7) * 8; \
                    *(uint4*)&sA[row * 72 + c8] = *(const uint4*)(srcA + (size_t)row * CINP + c8); \
                } \
            } \
            { \
                const __nv_bfloat16* srcB = wspl + (size_t)(img * 3 + split) * (COUTC * 64); \
                _Pragma("unroll") \
                for (int k = 0; k < COUTC / 32; k++) { \
                    const int ch = tid + k * 256; \
                    const int row = ch >> 3; \
                    const int c8 = (ch & 7) * 8; \
                    *(uint4*)&sB[row * 72 + c8] = *(const uint4*)(srcB + row * 64 + c8); \
                } \
            } \
            __syncthreads(); \
            _Pragma("unroll") \
            for (int k16 = 0; k16 < 4; k16++) { \
                const int kb = k16 * 16; \
                uint32_t a0 = *(const uint32_t*)&sA[(warp * 16 + gid) * 72 + kb + qid * 2]; \
                uint32_t a1 = *(const uint32_t*)&sA[(warp * 16 + gid + 8) * 72 + kb + qid * 2]; \
                uint32_t a2 = *(const uint32_t*)&sA[(warp * 16 + gid) * 72 + kb + 8 + qid * 2]; \
                uint32_t a3 = *(const uint32_t*)&sA[(warp * 16 + gid + 8) * 72 + kb + 8 + qid * 2]; \
                _Pragma("unroll") \
                for (int nt = 0; nt < COUTC / 8; nt++) { \
                    uint32_t b0 = *(const uint32_t*)&sB[(nt * 8 + gid) * 72 + kb + qid * 2]; \
                    uint32_t b1 = *(const uint32_t*)&sB[(nt * 8 + gid) * 72 + kb + 8 + qid * 2]; \
                    asm volatile( \
                        "mma.sync.aligned.m16n8k16.row.col.f32.bf16.bf16.f32 " \
                        "{%0,%1,%2,%3}, {%4,%5,%6,%7}, {%8,%9}, {%0,%1,%2,%3};" \
                        : "+f"(dacc[nt][0]), "+f"(dacc[nt][1]), \
                          "+f"(dacc[nt][2]), "+f"(dacc[nt][3]) \
                        : "r"(a0), "r"(a1), "r"(a2), "r"(a3), "r"(b0), "r"(b1)); \
                } \
            } \
        } \
    } \
    _Pragma("unroll") \
    for (int nt = 0; nt < COUTC / 8; nt++) { \
        const int col = nt * 8 + qid * 2; \
        const float bv0 = bias[col]; \
        const float bv1 = bias[col + 1]; \
        float* y0 = yout + ((size_t)pix * 1024 + m0 + warp * 16 + gid) * COUTC + col; \
        float* y1 = yout + ((size_t)pix * 1024 + m0 + warp * 16 + gid + 8) * COUTC + col; \
        *(float2*)y0 = make_float2(dacc[nt][0] + bv0, dacc[nt][1] + bv1); \
        *(float2*)y1 = make_float2(dacc[nt][2] + bv0, dacc[nt][3] + bv1); \
    } \
}

__global__ void __launch_bounds__(256) conv_hmma_c32(
    const __nv_bfloat16* __restrict__ inPad, const __nv_bfloat16* __restrict__ wspl,
    const float* __restrict__ bias, float* __restrict__ yout, int W)
CONV_HMMA_BODY(32, 1)

__global__ void __launch_bounds__(256) conv_hmma_c64(
    const __nv_bfloat16* __restrict__ inPad, const __nv_bfloat16* __restrict__ wspl,
    const float* __restrict__ bias, float* __restrict__ yout, int W)
CONV_HMMA_BODY(64, 1)

__global__ void __launch_bounds__(256) conv_hmma_c128(
    const __nv_bfloat16* __restrict__ inPad, const __nv_bfloat16* __restrict__ wspl,
    const float* __restrict__ bias, float* __restrict__ yout, int W)
CONV_HMMA_BODY(128, 1)

__global__ void __launch_bounds__(256) conv_hmma_c128k2(
    const __nv_bfloat16* __restrict__ inPad, const __nv_bfloat16* __restrict__ wspl,
    const float* __restrict__ bias, float* __restrict__ yout, int W)
CONV_HMMA_BODY(128, 2)

// ---------------------------------------------------------------------------
// conv1 scalar (proven), NCHW in/out, 128 imgs
// ---------------------------------------------------------------------------
__global__ void __launch_bounds__(256) conv1_kernel(
    const float* __restrict__ in, const float* __restrict__ wt,
    const float* __restrict__ bias, float* __restrict__ out)
{
    const int H = 32, W = 32, CIN = 3, COUT = 32;
    const int PW = 34, IN_TILE = 34 * 34, HW = 1024;
    __shared__ float s_in[3][34 * 34];
    __shared__ __align__(16) float s_w[3][9][8];
    const int tid = threadIdx.x;
    const int cog = blockIdx.y;
    const int m0 = blockIdx.x;
    for (int i = tid; i < 3 * IN_TILE; i += 256) {
        int c = i / IN_TILE, r = i % IN_TILE;
        int pyy = r / PW, pxx = r % PW, iy = pyy - 1, ix = pxx - 1;
        float v = 0.f;
        if (iy >= 0 && iy < H && ix >= 0 && ix < W)
            v = in[((size_t)m0 * CIN + c) * HW + iy * W + ix];
        s_in[c][r] = v;
    }
    if (tid < 72) {
        int j = tid / 9, k = tid % 9;
        for (int c = 0; c < 3; c++)
            s_w[c][k][j] = wt[((size_t)(cog * 8 + j) * CIN + c) * 9 + k];
    }
    __syncthreads();
    const int oy = (tid / 16) * 2, ox = (tid % 16) * 2;
    float acc[4][8];
#pragma unroll
    for (int p = 0; p < 4; p++)
#pragma unroll
        for (int j = 0; j < 8; j++) acc[p][j] = 0.f;
#pragma unroll
    for (int c = 0; c < 3; c++) {
        float xv[4][4];
        const float* sb = &s_in[c][oy * PW + ox];
#pragma unroll
        for (int dy = 0; dy < 4; dy++) {
            float2 a = *(const float2*)(sb + dy * PW);
            float2 b = *(const float2*)(sb + dy * PW + 2);
            xv[dy][0] = a.x; xv[dy][1] = a.y; xv[dy][2] = b.x; xv[dy][3] = b.y;
        }
#pragma unroll
        for (int k = 0; k < 9; k++) {
            const int ky = k / 3, kx = k % 3;
            float4 wlo = *(const float4*)&s_w[c][k][0];
            float4 whi = *(const float4*)&s_w[c][k][4];
            float w8[8] = {wlo.x, wlo.y, wlo.z, wlo.w, whi.x, whi.y, whi.z, whi.w};
#pragma unroll
            for (int pyy = 0; pyy < 2; pyy++)
#pragma unroll
                for (int pxx = 0; pxx < 2; pxx++) {
                    const float xvv = xv[pyy + ky][pxx + kx];
#pragma unroll
                    for (int j = 0; j < 8; j++)
                        acc[pyy * 2 + pxx][j] = fmaf(xvv, w8[j], acc[pyy * 2 + pxx][j]);
                }
        }
    }
#pragma unroll
    for (int j = 0; j < 8; j++) {
        float bj = bias[cog * 8 + j];
        const size_t base = ((size_t)m0 * COUT + cog * 8 + j) * HW;
#pragma unroll
        for (int pyy = 0; pyy < 2; pyy++)
            *(float2*)&out[base + (oy + pyy) * W + ox] =
                make_float2(acc[pyy * 2][j] + bj, acc[pyy * 2 + 1][j] + bj);
    }
}

// ---------------------------------------------------------------------------
// BN stats (deterministic two-stage fp64)
// ---------------------------------------------------------------------------
__global__ void bn_stats_nchw(const float* __restrict__ y, int C, int HW4, int M)
{
    const int c = blockIdx.x, b = blockIdx.y;
    const long total4 = (long)M * HW4;
    const long chunk = (total4 + NB - 1) / NB;
    long beg = (long)b * chunk;
    long end = beg + chunk;
    if (end > total4) end = total4;
    const float4* y4 = (const float4*)y;
    double s = 0.0, s2 = 0.0;
    for (long e = beg + threadIdx.x; e < end; e += 256) {
        long m = e / HW4;
        int off = (int)(e % HW4);
        float4 v = y4[((size_t)m * C + c) * HW4 + off];
        double a = v.x, bb = v.y, cc = v.z, dd = v.w;
        s += (a + bb) + (cc + dd);
        s2 += (a * a + bb * bb) + (cc * cc + dd * dd);
    }
    __shared__ double ss[256];
    __shared__ double qq[256];
    ss[threadIdx.x] = s;
    qq[threadIdx.x] = s2;
    __syncthreads();
    for (int st = 128; st > 0; st >>= 1) {
        if (threadIdx.x < st) {
            ss[threadIdx.x] += ss[threadIdx.x + st];
            qq[threadIdx.x] += qq[threadIdx.x + st];
        }
        __syncthreads();
    }
    if (threadIdx.x == 0) {
        g_ps[c * NB + b] = ss[0];
        g_ps2[c * NB + b] = qq[0];
    }
}

// channel-last stats: y [R rows][C]
__global__ void bn_stats_cl(const float* __restrict__ y, int C, long R)
{
    const int b = blockIdx.x;
    const int t = threadIdx.x;
    const int c = t % C;
    const int g = t / C;
    const int G = 256 / C;
    const long chunk = (R + NB - 1) / NB;
    long beg = (long)b * chunk;
    long end = beg + chunk;
    if (end > R) end = R;
    double s = 0.0, s2 = 0.0;
    for (long r = beg + g; r < end; r += G) {
        double v = (double)y[(size_t)r * C + c];
        s += v;
        s2 += v * v;
    }
    __shared__ double ss[256];
    __shared__ double qq[256];
    ss[t] = s;
    qq[t] = s2;
    __syncthreads();
    for (int st = G >> 1; st > 0; st >>= 1) {
        if (g < st) {
            ss[t] += ss[t + st * C];
            qq[t] += qq[t + st * C];
        }
        __syncthreads();
    }
    if (g == 0) {
        g_ps[c * NB + b] = ss[t];
        g_ps2[c * NB + b] = qq[t];
    }
}

__global__ void bn_finalize_kernel(const float* __restrict__ g,
                                   const float* __restrict__ be, int C, double n)
{
    int c = threadIdx.x;
    if (c >= C) return;
    double s = 0.0, s2 = 0.0;
    for (int b = 0; b < NB; b++) {
        s += g_ps[c * NB + b];
        s2 += g_ps2[c * NB + b];
    }
    double mean = s / n;
    double var = s2 / n - mean * mean;
    float invf = g[c] / sqrtf((float)var + 1e-5f);
    g_inv[c] = invf;
    g_shift[c] = be[c] - (float)mean * invf;
}

// ---------------------------------------------------------------------------
// L1: BN+LIF, NCHW y (t-invariant) -> padded CL spikes (CINP=64, Wp=34)
// ---------------------------------------------------------------------------
__global__ void bn_lif_l1(const float* __restrict__ y, __nv_bfloat16* __restrict__ out)
{
    const int idx = blockIdx.x * 256 + threadIdx.x;
    if (idx >= 128 * 1024 * 32) return;
    const int c = idx & 31;
    const int hw = (idx >> 5) & 1023;
    const int n = idx >> 15;
    const float x = fmaf(y[((size_t)n * 32 + c) * 1024 + hw], g_inv[c], g_shift[c]);
    const int pix = ((hw >> 5) + 1) * 34 + (hw & 31) + 1;
    float v = 0.f;
#pragma unroll
    for (int t = 0; t < TSTEPS; t++) {
        v = v + (x - v) * 0.5f;
        float sp = (v >= 1.0f) ? 1.0f : 0.0f;
        out[((size_t)pix * 1024 + t * 128 + n) * 64 + c] = __float2bfloat16(sp);
        if (v >= 1.0f) v = 0.0f;
    }
}

// BN+LIF (no pool): y CL [P][1024][C] -> padded spikes, width Wpn, depth CINP
__global__ void bn_lif_cl(const float* __restrict__ y, __nv_bfloat16* __restrict__ out,
                          int C, int W, int CINP, int Wpn)
{
    const int P = W * W;
    const int sites = P * 128 * C;
    const int idx = blockIdx.x * 256 + threadIdx.x;
    if (idx >= sites) return;
    const int c = idx % C;
    const int nimg = (idx / C) & 127;
    const int p = idx / (C * 128);
    const int pixo = (p / W + 1) * Wpn + (p % W) + 1;
    const float vi = g_inv[c], sh = g_shift[c];
    float v = 0.f;
#pragma unroll
    for (int t = 0; t < TSTEPS; t++) {
        float x = fmaf(y[((size_t)p * 1024 + t * 128 + nimg) * C + c], vi, sh);
        v = v + (x - v) * 0.5f;
        float sp = (v >= 1.0f) ? 1.0f : 0.0f;
        out[((size_t)pixo * 1024 + t * 128 + nimg) * CINP + c] = __float2bfloat16(sp);
        if (v >= 1.0f) v = 0.0f;
    }
}

// BN+LIF+2x2 maxpool; Wpn==0 -> no halo (fc input)
__global__ void bn_lif_pool_cl(const float* __restrict__ y, __nv_bfloat16* __restrict__ out,
                               int C, int W, int CINP, int Wpn)
{
    const int OW = W / 2;
    const int OP = OW * OW;
    const int sites = OP * 128 * C;
    const int idx = blockIdx.x * 256 + threadIdx.x;
    if (idx >= sites) return;
    const int c = idx % C;
    const int nimg = (idx / C) & 127;
    const int op = idx / (C * 128);
    const int oy = op / OW, ox = op % OW;
    const int p00 = (2 * oy) * W + 2 * ox;
    const int pixo = (Wpn != 0) ? ((oy + 1) * Wpn + ox + 1) : op;
    const float vi = g_inv[c], sh = g_shift[c];
    float v0 = 0.f, v1 = 0.f, v2 = 0.f, v3 = 0.f;
#pragma unroll
    for (int t = 0; t < TSTEPS; t++) {
        const size_t rb = ((size_t)t * 128 + nimg) * C + c;
        float x0 = fmaf(y[(size_t)p00 * 1024 * C + rb],           vi, sh);
        float x1 = fmaf(y[(size_t)(p00 + 1) * 1024 * C + rb],     vi, sh);
        float x2 = fmaf(y[(size_t)(p00 + W) * 1024 * C + rb],     vi, sh);
        float x3 = fmaf(y[(size_t)(p00 + W + 1) * 1024 * C + rb], vi, sh);
        v0 = v0 + (x0 - v0) * 0.5f;
        v1 = v1 + (x1 - v1) * 0.5f;
        v2 = v2 + (x2 - v2) * 0.5f;
        v3 = v3 + (x3 - v3) * 0.5f;
        float sp = ((v0 >= 1.f) || (v1 >= 1.f) || (v2 >= 1.f) || (v3 >= 1.f)) ? 1.f : 0.f;
        out[((size_t)pixo * 1024 + t * 128 + nimg) * CINP + c] = __float2bfloat16(sp);
        if (v0 >= 1.f) v0 = 0.f;
        if (v1 >= 1.f) v1 = 0.f;
        if (v2 >= 1.f) v2 = 0.f;
        if (v3 >= 1.f) v3 = 0.f;
    }
}

// ---------------------------------------------------------------------------
// fc1: in = [16 px][1024 tn][128 c] bf16; feature index = c*16 + p
// ---------------------------------------------------------------------------
__global__ void __launch_bounds__(128) fc1_kernel(
    const __nv_bfloat16* __restrict__ in, const float* __restrict__ w,
    const float* __restrict__ b, float* __restrict__ out)
{
    __shared__ float s_f[2048][4];
    const int r0 = blockIdx.x * 4;
    for (int i = threadIdx.x; i < 16 * 4 * 128; i += 128) {
        int p = i / 512;
        int rr = (i / 128) & 3;
        int c = i & 127;
        s_f[c * 16 + p][rr] = __bfloat162float(in[((size_t)p * 1024 + r0 + rr) * 128 + c]);
    }
    __syncthreads();
    const int o = threadIdx.x;
    const float4* wr = (const float4*)(w + (size_t)o * 2048);
    float a0 = 0.f, a1 = 0.f, a2 = 0.f, a3 = 0.f;
#pragma unroll 4
    for (int f4 = 0; f4 < 512; f4++) {
        float4 wv = wr[f4];
        const float* s0 = &s_f[f4 * 4][0];
        a0 = fmaf(s0[0], wv.x, fmaf(s0[4], wv.y, fmaf(s0[8],  wv.z, fmaf(s0[12], wv.w, a0))));
        a1 = fmaf(s0[1], wv.x, fmaf(s0[5], wv.y, fmaf(s0[9],  wv.z, fmaf(s0[13], wv.w, a1))));
        a2 = fmaf(s0[2], wv.x, fmaf(s0[6], wv.y, fmaf(s0[10], wv.z, fmaf(s0[14], wv.w, a2))));
        a3 = fmaf(s0[3], wv.x, fmaf(s0[7], wv.y, fmaf(s0[11], wv.z, fmaf(s0[15], wv.w, a3))));
    }
    const float bo = b[o];
    out[(size_t)(r0 + 0) * 128 + o] = a0 + bo;
    out[(size_t)(r0 + 1) * 128 + o] = a1 + bo;
    out[(size_t)(r0 + 2) * 128 + o] = a2 + bo;
    out[(size_t)(r0 + 3) * 128 + o] = a3 + bo;
}

__global__ void fc2_kernel(const float* __restrict__ in, const float* __restrict__ w,
                           const float* __restrict__ b, float* __restrict__ out)
{
    const int idx = blockIdx.x * 256 + threadIdx.x;
    if (idx >= 10240) return;
    const int r = idx / 10;
    const int o = idx % 10;
    const float4* ir = (const float4*)(in + (size_t)r * 128);
    const float4* wr = (const float4*)(w + (size_t)o * 128);
    float a = 0.f;
#pragma unroll
    for (int f = 0; f < 32; f++) {
        float4 x = ir[f];
        float4 wv = wr[f];
        a = fmaf(x.x, wv.x, fmaf(x.y, wv.y, fmaf(x.z, wv.z, fmaf(x.w, wv.w, a))));
    }
    out[idx] = a + b[o];
}

__global__ void lif_kernel(const float* __restrict__ y, float* __restrict__ s, int sites)
{
    const int idx = blockIdx.x * 256 + threadIdx.x;
    if (idx >= sites) return;
    float v = 0.f;
#pragma unroll
    for (int t = 0; t < TSTEPS; t++) {
        float x = y[(size_t)t * sites + idx];
        v = v + (x - v) * 0.5f;
        s[(size_t)t * sites + idx] = (v >= 1.0f) ? 1.0f : 0.0f;
        if (v >= 1.0f) v = 0.0f;
    }
}

__global__ void lif_mean_kernel(const float* __restrict__ y, float* __restrict__ out, int sites)
{
    const int idx = blockIdx.x * 256 + threadIdx.x;
    if (idx >= sites) return;
    float v = 0.f, cnt = 0.f;
#pragma unroll
    for (int t = 0; t < TSTEPS; t++) {
        float x = y[(size_t)t * sites + idx];
        v = v + (x - v) * 0.5f;
        if (v >= 1.0f) { cnt += 1.0f; v = 0.0f; }
    }
    out[idx] = cnt * 0.125f;
}

// ---------------------------------------------------------------------------
extern "C" void kernel_launch(void* const* d_in, const int* in_sizes, int n_in,
                              void* d_out, int out_size)
{
    const float* x = (const float*)d_in[0];
    const float* w[7];
    const float* bb[7];
    const float* gg[7];
    const float* be[7];
    for (int L = 1; L <= 6; L++) {
        w [L] = (const float*)d_in[1 + 4 * (L - 1) + 0];
        bb[L] = (const float*)d_in[1 + 4 * (L - 1) + 1];
        gg[L] = (const float*)d_in[1 + 4 * (L - 1) + 2];
        be[L] = (const float*)d_in[1 + 4 * (L - 1) + 3];
    }
    const float* fc1_w = (const float*)d_in[25];
    const float* fc1_b = (const float*)d_in[26];
    const float* fc2_w = (const float*)d_in[27];
    const float* fc2_b = (const float*)d_in[28];
    float* out = (float*)d_out;

    float* y = 0;
    float* f1 = 0;
    float* f1s = 0;
    float* f2 = 0;
    void* pav = 0;
    void* pbv = 0;
    void* wvp = 0;
    cudaGetSymbolAddress((void**)&y, g_y);
    cudaGetSymbolAddress(&pav, g_pA4);
    cudaGetSymbolAddress(&pbv, g_pB4);
    cudaGetSymbolAddress(&wvp, g_wsp4);
    cudaGetSymbolAddress((void**)&f1, g_fc1);
    cudaGetSymbolAddress((void**)&f1s, g_fc1s);
    cudaGetSymbolAddress((void**)&f2, g_fc2);
    __nv_bfloat16* pA = (__nv_bfloat16*)pav;
    __nv_bfloat16* pB = (__nv_bfloat16*)pbv;
    __nv_bfloat16* wsp = (__nv_bfloat16*)wvp;
    const size_t WO2 = 0;
    const size_t WO3 = 55296;
    const size_t WO4 = 165888;
    const size_t WO5 = 276480;
    const size_t WO6 = 497664;

    // weight prep (packed [img][split][COUT][64], exact 3-way split)
    wprep_kernel<<<64, 256>>>(w[2], wsp + WO2, 32, 32, 1);
    wprep_kernel<<<64, 256>>>(w[3], wsp + WO3, 64, 32, 1);
    wprep_kernel<<<64, 256>>>(w[4], wsp + WO4, 64, 64, 1);
    wprep_kernel<<<64, 256>>>(w[5], wsp + WO5, 128, 64, 1);
    wprep_kernel<<<128, 256>>>(w[6], wsp + WO6, 128, 128, 2);

    // ---- L1 (scalar conv over 128 imgs, NCHW) ----
    conv1_kernel<<<dim3(128, 4), 256>>>(x, w[1], bb[1], y);
    bn_stats_nchw<<<dim3(32, NB), 256>>>(y, 32, 256, 128);
    bn_finalize_kernel<<<1, 128>>>(gg[1], be[1], 32, 131072.0);
    cudaMemsetAsync(pA, 0, (size_t)1156 * 1024 * 64 * 2);
    bn_lif_l1<<<16384, 256>>>(y, pA);

    // ---- L2 ----
    conv_hmma_c32<<<dim3(1024, 8), 256>>>(pA, wsp + WO2, bb[2], y, 32);
    bn_stats_cl<<<NB, 256>>>(y, 32, (long)1024 * 1024);
    bn_finalize_kernel<<<1, 128>>>(gg[2], be[2], 32, 1048576.0);
    cudaMemsetAsync(pB, 0, (size_t)324 * 1024 * 64 * 2);
    bn_lif_pool_cl<<<4096, 256>>>(y, pB, 32, 32, 64, 18);

    // ---- L3 ----
    conv_hmma_c64<<<dim3(256, 8), 256>>>(pB, wsp + WO3, bb[3], y, 16);
    bn_stats_cl<<<NB, 256>>>(y, 64, (long)256 * 1024);
    bn_finalize_kernel<<<1, 128>>>(gg[3], be[3], 64, 262144.0);
    cudaMemsetAsync(pA, 0, (size_t)324 * 1024 * 64 * 2);
    bn_lif_cl<<<8192, 256>>>(y, pA, 64, 16, 64, 18);

    // ---- L4 ----
    conv_hmma_c64<<<dim3(256, 8), 256>>>(pA, wsp + WO4, bb[4], y, 16);
    bn_stats_cl<<<NB, 256>>>(y, 64, (long)256 * 1024);
    bn_finalize_kernel<<<1, 128>>>(gg[4], be[4], 64, 262144.0);
    cudaMemsetAsync(pB, 0, (size_t)100 * 1024 * 64 * 2);
    bn_lif_pool_cl<<<2048, 256>>>(y, pB, 64, 16, 64, 10);

    // ---- L5 ----
    conv_hmma_c128<<<dim3(64, 8), 256>>>(pB, wsp + WO5, bb[5], y, 8);
    bn_stats_cl<<<NB, 256>>>(y, 128, (long)64 * 1024);
    bn_finalize_kernel<<<1, 128>>>(gg[5], be[5], 128, 65536.0);
    cudaMemsetAsync(pA, 0, (size_t)100 * 1024 * 128 * 2);
    bn_lif_cl<<<4096, 256>>>(y, pA, 128, 8, 128, 10);

    // ---- L6 ----
    conv_hmma_c128k2<<<dim3(64, 8), 256>>>(pA, wsp + WO6, bb[6], y, 8);
    bn_stats_cl<<<NB, 256>>>(y, 128, (long)64 * 1024);
    bn_finalize_kernel<<<1, 128>>>(gg[6], be[6], 128, 65536.0);
    bn_lif_pool_cl<<<1024, 256>>>(y, pB, 128, 8, 128, 0);

    // ---- FC head ----
    fc1_kernel<<<256, 128>>>(pB, fc1_w, fc1_b, f1);
    lif_kernel<<<64, 256>>>(f1, f1s, 16384);
    fc2_kernel<<<40, 256>>>(f1s, fc2_w, fc2_b, f2);
    lif_mean_kernel<<<5, 256>>>(f2, out, 1280);
}

// round 17
// speedup vs baseline: 1.3150x; 1.1415x over previous
#include <cuda.h>
#include <cuda_runtime.h>
#include <cuda_bf16.h>
#include <math.h>
#include <cstdint>

#define TSTEPS 8
#define NB 256

// ---------------------------------------------------------------------------
// device scratch
// ---------------------------------------------------------------------------
__device__ float  g_y [33554432];      // conv pre-act, channel-last (128MB)
__device__ uint4  g_pA4[9500000];      // padded spike tensor A (152MB)
__device__ uint4  g_pB4[2700000];      // padded spike tensor B (43MB)
__device__ uint4  g_wsp4[125000];      // pre-split weights (2MB)
__device__ float  g_fc1[131072];
__device__ float  g_fc1s[131072];
__device__ float  g_fc2[10240];
__device__ double g_ps [128 * NB];
__device__ double g_ps2[128 * NB];
__device__ float  g_inv[128];
__device__ float  g_shift[128];

// ---------------------------------------------------------------------------
// weight prep: fp32 w[co][ci][3][3] -> images ordered (img = tap*KC+kc, split),
// each packed [COUT][KELEM] bf16 row-major.  Exact 3-way split (w = b0+b1+b2).
// ---------------------------------------------------------------------------
__global__ void wprep_kernel(const float* __restrict__ w, __nv_bfloat16* __restrict__ dst,
                             int COUT, int CINR, int KELEM, int KC)
{
    const int per = COUT * KELEM;
    const int total = 9 * KC * per;
    for (int i = blockIdx.x * 256 + threadIdx.x; i < total; i += gridDim.x * 256) {
        const int img = i / per;
        const int rr = i % per;
        const int tap = img / KC;
        const int kc = img % KC;
        const int co = rr / KELEM;
        const int cil = rr % KELEM;
        const int ci = kc * KELEM + cil;
        float wv = 0.f;
        if (ci < CINR) wv = w[((size_t)co * CINR + ci) * 9 + tap];
        __nv_bfloat16 b0 = __float2bfloat16(wv);
        float r1 = wv - __bfloat162float(b0);
        __nv_bfloat16 b1 = __float2bfloat16(r1);
        __nv_bfloat16 b2 = __float2bfloat16(r1 - __bfloat162float(b1));
        dst[(size_t)(img * 3 + 0) * per + co * (size_t)KELEM + cil] = b0;
        dst[(size_t)(img * 3 + 1) * per + co * (size_t)KELEM + cil] = b1;
        dst[(size_t)(img * 3 + 2) * per + co * (size_t)KELEM + cil] = b2;
    }
}

// ---------------------------------------------------------------------------
// conv via warp-level HMMA (mma.sync m16n8k16 bf16->f32).
// CTA = 1 output pixel x one 128-row tn tile; 8 warps x m16.
// Per (tap,kc): stage A [128 x KELEM] once + B for ALL 3 splits of one n-group,
// hoist A fragments out of the split loop.  Products exact (spikes in {0,1}).
// ---------------------------------------------------------------------------
#define CONV_HMMA_BODY(COUTC, KELEM, KC) \
{ \
    enum { SAE = (KELEM) + 8, \
           NPG = ((COUTC) > 64 ? 64 : (COUTC)), \
           NGR = (COUTC) / NPG, \
           NK16 = (KELEM) / 16, \
           NTG = NPG / 8, \
           ACH = 128 * (KELEM) / 8, \
           KCH = (KELEM) / 8, \
           BCH = 3 * NPG * (KELEM) / 8 }; \
    __shared__ __align__(16) __nv_bfloat16 sA[128 * SAE]; \
    __shared__ __align__(16) __nv_bfloat16 sB[3 * NPG * SAE]; \
    const int tid = threadIdx.x; \
    const int warp = tid >> 5; \
    const int lane = tid & 31; \
    const int gid = lane >> 2; \
    const int qid = lane & 3; \
    const int pix = blockIdx.x; \
    const int m0 = blockIdx.y * 128; \
    const int py = pix / W; \
    const int px = pix % W; \
    const int Wp = W + 2; \
    const int CINP = (KC) * (KELEM); \
    float dacc[(COUTC) / 8][4]; \
    _Pragma("unroll") \
    for (int nt = 0; nt < (COUTC) / 8; nt++) { \
        dacc[nt][0] = 0.f; dacc[nt][1] = 0.f; dacc[nt][2] = 0.f; dacc[nt][3] = 0.f; \
    } \
    for (int img = 0; img < 9 * (KC); img++) { \
        const int tap = img / (KC); \
        const int kc = img % (KC); \
        const int ky = tap / 3; \
        const int kx = tap % 3; \
        const __nv_bfloat16* srcA = inPad \
            + ((size_t)((py + ky) * Wp + (px + kx)) * 1024 + m0) * (size_t)CINP + kc * (KELEM); \
        for (int g = 0; g < NGR; g++) { \
            __syncthreads(); \
            if (g == 0) { \
                _Pragma("unroll") \
                for (int k = 0; k < ACH / 256; k++) { \
                    const int ch = tid + k * 256; \
                    const int row = ch / KCH; \
                    const int c8 = (ch % KCH) * 8; \
                    *(uint4*)&sA[row * SAE + c8] = *(const uint4*)(srcA + (size_t)row * CINP + c8); \
                } \
            } \
            { \
                const __nv_bfloat16* srcB = wspl + (size_t)img * 3 * (COUTC) * (KELEM); \
                for (int ch = tid; ch < BCH; ch += 256) { \
                    const int s = ch / (NPG * KCH); \
                    const int r = ch % (NPG * KCH); \
                    const int co = r / KCH; \
                    const int c8 = (r % KCH) * 8; \
                    *(uint4*)&sB[(s * NPG + co) * SAE + c8] = \
                        *(const uint4*)(srcB + (size_t)s * (COUTC) * (KELEM) \
                                        + (size_t)(g * NPG + co) * (KELEM) + c8); \
                } \
            } \
            __syncthreads(); \
            _Pragma("unroll") \
            for (int k16 = 0; k16 < NK16; k16++) { \
                const int kb = k16 * 16; \
                uint32_t a0 = *(const uint32_t*)&sA[(warp * 16 + gid) * SAE + kb + qid * 2]; \
                uint32_t a1 = *(const uint32_t*)&sA[(warp * 16 + gid + 8) * SAE + kb + qid * 2]; \
                uint32_t a2 = *(const uint32_t*)&sA[(warp * 16 + gid) * SAE + kb + 8 + qid * 2]; \
                uint32_t a3 = *(const uint32_t*)&sA[(warp * 16 + gid + 8) * SAE + kb + 8 + qid * 2]; \
                _Pragma("unroll") \
                for (int ntl = 0; ntl < NTG; ntl++) { \
                    const int nt = g * NTG + ntl; \
                    _Pragma("unroll") \
                    for (int s = 0; s < 3; s++) { \
                        uint32_t b0 = *(const uint32_t*)&sB[(s * NPG + ntl * 8 + gid) * SAE + kb + qid * 2]; \
                        uint32_t b1 = *(const uint32_t*)&sB[(s * NPG + ntl * 8 + gid) * SAE + kb + 8 + qid * 2]; \
                        asm volatile( \
                            "mma.sync.aligned.m16n8k16.row.col.f32.bf16.bf16.f32 " \
                            "{%0,%1,%2,%3}, {%4,%5,%6,%7}, {%8,%9}, {%0,%1,%2,%3};" \
                            : "+f"(dacc[nt][0]), "+f"(dacc[nt][1]), \
                              "+f"(dacc[nt][2]), "+f"(dacc[nt][3]) \
                            : "r"(a0), "r"(a1), "r"(a2), "r"(a3), "r"(b0), "r"(b1)); \
                    } \
                } \
            } \
        } \
    } \
    _Pragma("unroll") \
    for (int nt = 0; nt < (COUTC) / 8; nt++) { \
        const int col = nt * 8 + qid * 2; \
        const float bv0 = bias[col]; \
        const float bv1 = bias[col + 1]; \
        float* y0 = yout + ((size_t)pix * 1024 + m0 + warp * 16 + gid) * (COUTC) + col; \
        float* y1 = yout + ((size_t)pix * 1024 + m0 + warp * 16 + gid + 8) * (COUTC) + col; \
        *(float2*)y0 = make_float2(dacc[nt][0] + bv0, dacc[nt][1] + bv1); \
        *(float2*)y1 = make_float2(dacc[nt][2] + bv0, dacc[nt][3] + bv1); \
    } \
}

__global__ void __launch_bounds__(256) conv_hmma_c32k32(
    const __nv_bfloat16* __restrict__ inPad, const __nv_bfloat16* __restrict__ wspl,
    const float* __restrict__ bias, float* __restrict__ yout, int W)
CONV_HMMA_BODY(32, 32, 1)

__global__ void __launch_bounds__(256) conv_hmma_c64k32(
    const __nv_bfloat16* __restrict__ inPad, const __nv_bfloat16* __restrict__ wspl,
    const float* __restrict__ bias, float* __restrict__ yout, int W)
CONV_HMMA_BODY(64, 32, 1)

__global__ void __launch_bounds__(256) conv_hmma_c64k64(
    const __nv_bfloat16* __restrict__ inPad, const __nv_bfloat16* __restrict__ wspl,
    const float* __restrict__ bias, float* __restrict__ yout, int W)
CONV_HMMA_BODY(64, 64, 1)

__global__ void __launch_bounds__(256) conv_hmma_c128k64(
    const __nv_bfloat16* __restrict__ inPad, const __nv_bfloat16* __restrict__ wspl,
    const float* __restrict__ bias, float* __restrict__ yout, int W)
CONV_HMMA_BODY(128, 64, 1)

__global__ void __launch_bounds__(256) conv_hmma_c128k64x2(
    const __nv_bfloat16* __restrict__ inPad, const __nv_bfloat16* __restrict__ wspl,
    const float* __restrict__ bias, float* __restrict__ yout, int W)
CONV_HMMA_BODY(128, 64, 2)

// ---------------------------------------------------------------------------
// conv1 scalar (proven), NCHW in/out, 128 imgs
// ---------------------------------------------------------------------------
__global__ void __launch_bounds__(256) conv1_kernel(
    const float* __restrict__ in, const float* __restrict__ wt,
    const float* __restrict__ bias, float* __restrict__ out)
{
    const int H = 32, W = 32, CIN = 3, COUT = 32;
    const int PW = 34, IN_TILE = 34 * 34, HW = 1024;
    __shared__ float s_in[3][34 * 34];
    __shared__ __align__(16) float s_w[3][9][8];
    const int tid = threadIdx.x;
    const int cog = blockIdx.y;
    const int m0 = blockIdx.x;
    for (int i = tid; i < 3 * IN_TILE; i += 256) {
        int c = i / IN_TILE, r = i % IN_TILE;
        int pyy = r / PW, pxx = r % PW, iy = pyy - 1, ix = pxx - 1;
        float v = 0.f;
        if (iy >= 0 && iy < H && ix >= 0 && ix < W)
            v = in[((size_t)m0 * CIN + c) * HW + iy * W + ix];
        s_in[c][r] = v;
    }
    if (tid < 72) {
        int j = tid / 9, k = tid % 9;
        for (int c = 0; c < 3; c++)
            s_w[c][k][j] = wt[((size_t)(cog * 8 + j) * CIN + c) * 9 + k];
    }
    __syncthreads();
    const int oy = (tid / 16) * 2, ox = (tid % 16) * 2;
    float acc[4][8];
#pragma unroll
    for (int p = 0; p < 4; p++)
#pragma unroll
        for (int j = 0; j < 8; j++) acc[p][j] = 0.f;
#pragma unroll
    for (int c = 0; c < 3; c++) {
        float xv[4][4];
        const float* sb = &s_in[c][oy * PW + ox];
#pragma unroll
        for (int dy = 0; dy < 4; dy++) {
            float2 a = *(const float2*)(sb + dy * PW);
            float2 b = *(const float2*)(sb + dy * PW + 2);
            xv[dy][0] = a.x; xv[dy][1] = a.y; xv[dy][2] = b.x; xv[dy][3] = b.y;
        }
#pragma unroll
        for (int k = 0; k < 9; k++) {
            const int ky = k / 3, kx = k % 3;
            float4 wlo = *(const float4*)&s_w[c][k][0];
            float4 whi = *(const float4*)&s_w[c][k][4];
            float w8[8] = {wlo.x, wlo.y, wlo.z, wlo.w, whi.x, whi.y, whi.z, whi.w};
#pragma unroll
            for (int pyy = 0; pyy < 2; pyy++)
#pragma unroll
                for (int pxx = 0; pxx < 2; pxx++) {
                    const float xvv = xv[pyy + ky][pxx + kx];
#pragma unroll
                    for (int j = 0; j < 8; j++)
                        acc[pyy * 2 + pxx][j] = fmaf(xvv, w8[j], acc[pyy * 2 + pxx][j]);
                }
        }
    }
#pragma unroll
    for (int j = 0; j < 8; j++) {
        float bj = bias[cog * 8 + j];
        const size_t base = ((size_t)m0 * COUT + cog * 8 + j) * HW;
#pragma unroll
        for (int pyy = 0; pyy < 2; pyy++)
            *(float2*)&out[base + (oy + pyy) * W + ox] =
                make_float2(acc[pyy * 2][j] + bj, acc[pyy * 2 + 1][j] + bj);
    }
}

// ---------------------------------------------------------------------------
// BN stats (deterministic two-stage fp64)
// ---------------------------------------------------------------------------
__global__ void bn_stats_nchw(const float* __restrict__ y, int C, int HW4, int M)
{
    const int c = blockIdx.x, b = blockIdx.y;
    const long total4 = (long)M * HW4;
    const long chunk = (total4 + NB - 1) / NB;
    long beg = (long)b * chunk;
    long end = beg + chunk;
    if (end > total4) end = total4;
    const float4* y4 = (const float4*)y;
    double s = 0.0, s2 = 0.0;
    for (long e = beg + threadIdx.x; e < end; e += 256) {
        long m = e / HW4;
        int off = (int)(e % HW4);
        float4 v = y4[((size_t)m * C + c) * HW4 + off];
        double a = v.x, bb = v.y, cc = v.z, dd = v.w;
        s += (a + bb) + (cc + dd);
        s2 += (a * a + bb * bb) + (cc * cc + dd * dd);
    }
    __shared__ double ss[256];
    __shared__ double qq[256];
    ss[threadIdx.x] = s;
    qq[threadIdx.x] = s2;
    __syncthreads();
    for (int st = 128; st > 0; st >>= 1) {
        if (threadIdx.x < st) {
            ss[threadIdx.x] += ss[threadIdx.x + st];
            qq[threadIdx.x] += qq[threadIdx.x + st];
        }
        __syncthreads();
    }
    if (threadIdx.x == 0) {
        g_ps[c * NB + b] = ss[0];
        g_ps2[c * NB + b] = qq[0];
    }
}

// channel-last stats: y [R rows][C]
__global__ void bn_stats_cl(const float* __restrict__ y, int C, long R)
{
    const int b = blockIdx.x;
    const int t = threadIdx.x;
    const int c = t % C;
    const int g = t / C;
    const int G = 256 / C;
    const long chunk = (R + NB - 1) / NB;
    long beg = (long)b * chunk;
    long end = beg + chunk;
    if (end > R) end = R;
    double s = 0.0, s2 = 0.0;
    for (long r = beg + g; r < end; r += G) {
        double v = (double)y[(size_t)r * C + c];
        s += v;
        s2 += v * v;
    }
    __shared__ double ss[256];
    __shared__ double qq[256];
    ss[t] = s;
    qq[t] = s2;
    __syncthreads();
    for (int st = G >> 1; st > 0; st >>= 1) {
        if (g < st) {
            ss[t] += ss[t + st * C];
            qq[t] += qq[t + st * C];
        }
        __syncthreads();
    }
    if (g == 0) {
        g_ps[c * NB + b] = ss[t];
        g_ps2[c * NB + b] = qq[t];
    }
}

__global__ void bn_finalize_kernel(const float* __restrict__ g,
                                   const float* __restrict__ be, int C, double n)
{
    int c = threadIdx.x;
    if (c >= C) return;
    double s = 0.0, s2 = 0.0;
    for (int b = 0; b < NB; b++) {
        s += g_ps[c * NB + b];
        s2 += g_ps2[c * NB + b];
    }
    double mean = s / n;
    double var = s2 / n - mean * mean;
    float invf = g[c] / sqrtf((float)var + 1e-5f);
    g_inv[c] = invf;
    g_shift[c] = be[c] - (float)mean * invf;
}

// ---------------------------------------------------------------------------
// L1: BN+LIF, NCHW y (t-invariant) -> padded CL spikes (CINP=32, Wp=34)
// ---------------------------------------------------------------------------
__global__ void bn_lif_l1(const float* __restrict__ y, __nv_bfloat16* __restrict__ out)
{
    const int idx = blockIdx.x * 256 + threadIdx.x;
    if (idx >= 128 * 1024 * 32) return;
    const int c = idx & 31;
    const int hw = (idx >> 5) & 1023;
    const int n = idx >> 15;
    const float x = fmaf(y[((size_t)n * 32 + c) * 1024 + hw], g_inv[c], g_shift[c]);
    const int pix = ((hw >> 5) + 1) * 34 + (hw & 31) + 1;
    float v = 0.f;
#pragma unroll
    for (int t = 0; t < TSTEPS; t++) {
        v = v + (x - v) * 0.5f;
        float sp = (v >= 1.0f) ? 1.0f : 0.0f;
        out[((size_t)pix * 1024 + t * 128 + n) * 32 + c] = __float2bfloat16(sp);
        if (v >= 1.0f) v = 0.0f;
    }
}

// BN+LIF (no pool): y CL [P][1024][C] -> padded spikes, width Wpn, depth CINP
__global__ void bn_lif_cl(const float* __restrict__ y, __nv_bfloat16* __restrict__ out,
                          int C, int W, int CINP, int Wpn)
{
    const int P = W * W;
    const int sites = P * 128 * C;
    const int idx = blockIdx.x * 256 + threadIdx.x;
    if (idx >= sites) return;
    const int c = idx % C;
    const int nimg = (idx / C) & 127;
    const int p = idx / (C * 128);
    const int pixo = (p / W + 1) * Wpn + (p % W) + 1;
    const float vi = g_inv[c], sh = g_shift[c];
    float v = 0.f;
#pragma unroll
    for (int t = 0; t < TSTEPS; t++) {
        float x = fmaf(y[((size_t)p * 1024 + t * 128 + nimg) * C + c], vi, sh);
        v = v + (x - v) * 0.5f;
        float sp = (v >= 1.0f) ? 1.0f : 0.0f;
        out[((size_t)pixo * 1024 + t * 128 + nimg) * CINP + c] = __float2bfloat16(sp);
        if (v >= 1.0f) v = 0.0f;
    }
}

// BN+LIF+2x2 maxpool; Wpn==0 -> no halo (fc input)
__global__ void bn_lif_pool_cl(const float* __restrict__ y, __nv_bfloat16* __restrict__ out,
                               int C, int W, int CINP, int Wpn)
{
    const int OW = W / 2;
    const int OP = OW * OW;
    const int sites = OP * 128 * C;
    const int idx = blockIdx.x * 256 + threadIdx.x;
    if (idx >= sites) return;
    const int c = idx % C;
    const int nimg = (idx / C) & 127;
    const int op = idx / (C * 128);
    const int oy = op / OW, ox = op % OW;
    const int p00 = (2 * oy) * W + 2 * ox;
    const int pixo = (Wpn != 0) ? ((oy + 1) * Wpn + ox + 1) : op;
    const float vi = g_inv[c], sh = g_shift[c];
    float v0 = 0.f, v1 = 0.f, v2 = 0.f, v3 = 0.f;
#pragma unroll
    for (int t = 0; t < TSTEPS; t++) {
        const size_t rb = ((size_t)t * 128 + nimg) * C + c;
        float x0 = fmaf(y[(size_t)p00 * 1024 * C + rb],           vi, sh);
        float x1 = fmaf(y[(size_t)(p00 + 1) * 1024 * C + rb],     vi, sh);
        float x2 = fmaf(y[(size_t)(p00 + W) * 1024 * C + rb],     vi, sh);
        float x3 = fmaf(y[(size_t)(p00 + W + 1) * 1024 * C + rb], vi, sh);
        v0 = v0 + (x0 - v0) * 0.5f;
        v1 = v1 + (x1 - v1) * 0.5f;
        v2 = v2 + (x2 - v2) * 0.5f;
        v3 = v3 + (x3 - v3) * 0.5f;
        float sp = ((v0 >= 1.f) || (v1 >= 1.f) || (v2 >= 1.f) || (v3 >= 1.f)) ? 1.f : 0.f;
        out[((size_t)pixo * 1024 + t * 128 + nimg) * CINP + c] = __float2bfloat16(sp);
        if (v0 >= 1.f) v0 = 0.f;
        if (v1 >= 1.f) v1 = 0.f;
        if (v2 >= 1.f) v2 = 0.f;
        if (v3 >= 1.f) v3 = 0.f;
    }
}

// ---------------------------------------------------------------------------
// fc1: in = [16 px][1024 tn][128 c] bf16; feature index = c*16 + p
// ---------------------------------------------------------------------------
__global__ void __launch_bounds__(128) fc1_kernel(
    const __nv_bfloat16* __restrict__ in, const float* __restrict__ w,
    const float* __restrict__ b, float* __restrict__ out)
{
    __shared__ float s_f[2048][4];
    const int r0 = blockIdx.x * 4;
    for (int i = threadIdx.x; i < 16 * 4 * 128; i += 128) {
        int p = i / 512;
        int rr = (i / 128) & 3;
        int c = i & 127;
        s_f[c * 16 + p][rr] = __bfloat162float(in[((size_t)p * 1024 + r0 + rr) * 128 + c]);
    }
    __syncthreads();
    const int o = threadIdx.x;
    const float4* wr = (const float4*)(w + (size_t)o * 2048);
    float a0 = 0.f, a1 = 0.f, a2 = 0.f, a3 = 0.f;
#pragma unroll 4
    for (int f4 = 0; f4 < 512; f4++) {
        float4 wv = wr[f4];
        const float* s0 = &s_f[f4 * 4][0];
        a0 = fmaf(s0[0], wv.x, fmaf(s0[4], wv.y, fmaf(s0[8],  wv.z, fmaf(s0[12], wv.w, a0))));
        a1 = fmaf(s0[1], wv.x, fmaf(s0[5], wv.y, fmaf(s0[9],  wv.z, fmaf(s0[13], wv.w, a1))));
        a2 = fmaf(s0[2], wv.x, fmaf(s0[6], wv.y, fmaf(s0[10], wv.z, fmaf(s0[14], wv.w, a2))));
        a3 = fmaf(s0[3], wv.x, fmaf(s0[7], wv.y, fmaf(s0[11], wv.z, fmaf(s0[15], wv.w, a3))));
    }
    const float bo = b[o];
    out[(size_t)(r0 + 0) * 128 + o] = a0 + bo;
    out[(size_t)(r0 + 1) * 128 + o] = a1 + bo;
    out[(size_t)(r0 + 2) * 128 + o] = a2 + bo;
    out[(size_t)(r0 + 3) * 128 + o] = a3 + bo;
}

__global__ void fc2_kernel(const float* __restrict__ in, const float* __restrict__ w,
                           const float* __restrict__ b, float* __restrict__ out)
{
    const int idx = blockIdx.x * 256 + threadIdx.x;
    if (idx >= 10240) return;
    const int r = idx / 10;
    const int o = idx % 10;
    const float4* ir = (const float4*)(in + (size_t)r * 128);
    const float4* wr = (const float4*)(w + (size_t)o * 128);
    float a = 0.f;
#pragma unroll
    for (int f = 0; f < 32; f++) {
        float4 x = ir[f];
        float4 wv = wr[f];
        a = fmaf(x.x, wv.x, fmaf(x.y, wv.y, fmaf(x.z, wv.z, fmaf(x.w, wv.w, a))));
    }
    out[idx] = a + b[o];
}

__global__ void lif_kernel(const float* __restrict__ y, float* __restrict__ s, int sites)
{
    const int idx = blockIdx.x * 256 + threadIdx.x;
    if (idx >= sites) return;
    float v = 0.f;
#pragma unroll
    for (int t = 0; t < TSTEPS; t++) {
        float x = y[(size_t)t * sites + idx];
        v = v + (x - v) * 0.5f;
        s[(size_t)t * sites + idx] = (v >= 1.0f) ? 1.0f : 0.0f;
        if (v >= 1.0f) v = 0.0f;
    }
}

__global__ void lif_mean_kernel(const float* __restrict__ y, float* __restrict__ out, int sites)
{
    const int idx = blockIdx.x * 256 + threadIdx.x;
    if (idx >= sites) return;
    float v = 0.f, cnt = 0.f;
#pragma unroll
    for (int t = 0; t < TSTEPS; t++) {
        float x = y[(size_t)t * sites + idx];
        v = v + (x - v) * 0.5f;
        if (v >= 1.0f) { cnt += 1.0f; v = 0.0f; }
    }
    out[idx] = cnt * 0.125f;
}

// ---------------------------------------------------------------------------
extern "C" void kernel_launch(void* const* d_in, const int* in_sizes, int n_in,
                              void* d_out, int out_size)
{
    const float* x = (const float*)d_in[0];
    const float* w[7];
    const float* bb[7];
    const float* gg[7];
    const float* be[7];
    for (int L = 1; L <= 6; L++) {
        w [L] = (const float*)d_in[1 + 4 * (L - 1) + 0];
        bb[L] = (const float*)d_in[1 + 4 * (L - 1) + 1];
        gg[L] = (const float*)d_in[1 + 4 * (L - 1) + 2];
        be[L] = (const float*)d_in[1 + 4 * (L - 1) + 3];
    }
    const float* fc1_w = (const float*)d_in[25];
    const float* fc1_b = (const float*)d_in[26];
    const float* fc2_w = (const float*)d_in[27];
    const float* fc2_b = (const float*)d_in[28];
    float* out = (float*)d_out;

    float* y = 0;
    float* f1 = 0;
    float* f1s = 0;
    float* f2 = 0;
    void* pav = 0;
    void* pbv = 0;
    void* wvp = 0;
    cudaGetSymbolAddress((void**)&y, g_y);
    cudaGetSymbolAddress(&pav, g_pA4);
    cudaGetSymbolAddress(&pbv, g_pB4);
    cudaGetSymbolAddress(&wvp, g_wsp4);
    cudaGetSymbolAddress((void**)&f1, g_fc1);
    cudaGetSymbolAddress((void**)&f1s, g_fc1s);
    cudaGetSymbolAddress((void**)&f2, g_fc2);
    __nv_bfloat16* pA = (__nv_bfloat16*)pav;
    __nv_bfloat16* pB = (__nv_bfloat16*)pbv;
    __nv_bfloat16* wsp = (__nv_bfloat16*)wvp;
    // weight image offsets (bf16 elems)
    const size_t WO2 = 0;            // 9*3*32*32   = 27648
    const size_t WO3 = 27648;        // 9*3*64*32   = 55296
    const size_t WO4 = 82944;        // 9*3*64*64   = 110592
    const size_t WO5 = 193536;       // 9*3*128*64  = 221184
    const size_t WO6 = 414720;       // 18*3*128*64 = 442368

    // weight prep (packed [img][split][COUT][KELEM], exact 3-way split)
    wprep_kernel<<<64, 256>>>(w[2], wsp + WO2, 32, 32, 32, 1);
    wprep_kernel<<<64, 256>>>(w[3], wsp + WO3, 64, 32, 32, 1);
    wprep_kernel<<<64, 256>>>(w[4], wsp + WO4, 64, 64, 64, 1);
    wprep_kernel<<<64, 256>>>(w[5], wsp + WO5, 128, 64, 64, 1);
    wprep_kernel<<<128, 256>>>(w[6], wsp + WO6, 128, 128, 64, 2);

    // ---- L1 (scalar conv over 128 imgs, NCHW) ----
    conv1_kernel<<<dim3(128, 4), 256>>>(x, w[1], bb[1], y);
    bn_stats_nchw<<<dim3(32, NB), 256>>>(y, 32, 256, 128);
    bn_finalize_kernel<<<1, 128>>>(gg[1], be[1], 32, 131072.0);
    cudaMemsetAsync(pA, 0, (size_t)1156 * 1024 * 32 * 2);
    bn_lif_l1<<<16384, 256>>>(y, pA);

    // ---- L2 (CINP=32) ----
    conv_hmma_c32k32<<<dim3(1024, 8), 256>>>(pA, wsp + WO2, bb[2], y, 32);
    bn_stats_cl<<<NB, 256>>>(y, 32, (long)1024 * 1024);
    bn_finalize_kernel<<<1, 128>>>(gg[2], be[2], 32, 1048576.0);
    cudaMemsetAsync(pB, 0, (size_t)324 * 1024 * 32 * 2);
    bn_lif_pool_cl<<<4096, 256>>>(y, pB, 32, 32, 32, 18);

    // ---- L3 (CINP=32) ----
    conv_hmma_c64k32<<<dim3(256, 8), 256>>>(pB, wsp + WO3, bb[3], y, 16);
    bn_stats_cl<<<NB, 256>>>(y, 64, (long)256 * 1024);
    bn_finalize_kernel<<<1, 128>>>(gg[3], be[3], 64, 262144.0);
    cudaMemsetAsync(pA, 0, (size_t)324 * 1024 * 64 * 2);
    bn_lif_cl<<<8192, 256>>>(y, pA, 64, 16, 64, 18);

    // ---- L4 (CINP=64) ----
    conv_hmma_c64k64<<<dim3(256, 8), 256>>>(pA, wsp + WO4, bb[4], y, 16);
    bn_stats_cl<<<NB, 256>>>(y, 64, (long)256 * 1024);
    bn_finalize_kernel<<<1, 128>>>(gg[4], be[4], 64, 262144.0);
    cudaMemsetAsync(pB, 0, (size_t)100 * 1024 * 64 * 2);
    bn_lif_pool_cl<<<2048, 256>>>(y, pB, 64, 16, 64, 10);

    // ---- L5 (CINP=64) ----
    conv_hmma_c128k64<<<dim3(64, 8), 256>>>(pB, wsp + WO5, bb[5], y, 8);
    bn_stats_cl<<<NB, 256>>>(y, 128, (long)64 * 1024);
    bn_finalize_kernel<<<1, 128>>>(gg[5], be[5], 128, 65536.0);
    cudaMemsetAsync(pA, 0, (size_t)100 * 1024 * 128 * 2);
    bn_lif_cl<<<4096, 256>>>(y, pA, 128, 8, 128, 10);

    // ---- L6 (CINP=128 = 2 x 64) ----
    conv_hmma_c128k64x2<<<dim3(64, 8), 256>>>(pA, wsp + WO6, bb[6], y, 8);
    bn_stats_cl<<<NB, 256>>>(y, 128, (long)64 * 1024);
    bn_finalize_kernel<<<1, 128>>>(gg[6], be[6], 128, 65536.0);
    bn_lif_pool_cl<<<1024, 256>>>(y, pB, 128, 8, 128, 0);

    // ---- FC head ----
    fc1_kernel<<<256, 128>>>(pB, fc1_w, fc1_b, f1);
    lif_kernel<<<64, 256>>>(f1, f1s, 16384);
    fc2_kernel<<<40, 256>>>(f1s, fc2_w, fc2_b, f2);
    lif_mean_kernel<<<5, 256>>>(f2, out, 1280);
}